// round 5
// baseline (speedup 1.0000x reference)
#include <cuda_runtime.h>
#include <cstdint>

// ---------------- problem constants ----------------
#define NMAX 10000
#define EMAX 640000
#define DDIM 128
#define EDIM 64
#define HDS  8
#define OUTD 128

// ---------------- device scratch ----------------
__device__ __align__(16) float g_q[NMAX * DDIM];
__device__ __align__(16) float g_k[NMAX * DDIM];
__device__ __align__(16) float g_u[NMAX * OUTD];
__device__ __align__(16) float g_v[NMAX * OUTD];
__device__ __align__(16) float g_P[NMAX * HDS * OUTD];
__device__ __align__(16) float g_a[EMAX * HDS];     // exp(logit), indexed by SORTED position
__device__ __align__(16) float g_s[NMAX * HDS];     // segment sums -> 0.25/(s+eps)
__device__ __align__(16) float g_WcT[OUTD * OUTD];
__device__ __align__(16) float2 g_wdup[EDIM * DDIM]; // wdup[jj][d] = {Wre[d][jj], Wre[d][jj]}
__device__ int g_is64;
__device__ int g_nj[EMAX];
__device__ int g_ni[EMAX];
__device__ int g_cnt[NMAX];
__device__ int g_start[NMAX + 1];
__device__ int g_off[NMAX];
__device__ int g_elist[EMAX];   // sorted (by nj) -> original edge id
__device__ int g_nis[EMAX];     // ni by sorted position
__device__ int g_njs[EMAX];     // nj by sorted position

// ---------------- helpers ----------------
__device__ __forceinline__ unsigned long long pack2(float x) {
    unsigned long long r; unsigned u = __float_as_uint(x);
    asm("mov.b64 %0, {%1, %1};" : "=l"(r) : "r"(u));
    return r;
}
__device__ __forceinline__ void fma2(unsigned long long& d, unsigned long long a, unsigned long long b) {
    asm("fma.rn.f32x2 %0, %1, %2, %0;" : "+l"(d) : "l"(a), "l"(b));
}
__device__ __forceinline__ void unpack2(unsigned long long v, float& x, float& y) {
    unsigned a, b;
    asm("mov.b64 {%0, %1}, %2;" : "=r"(a), "=r"(b) : "l"(v));
    x = __uint_as_float(a); y = __uint_as_float(b);
}
__device__ __forceinline__ float siluf(float x) { return x / (1.0f + __expf(-x)); }
__device__ __forceinline__ int load_idx(const void* eidx, int is64, long long pos) {
    return is64 ? (int)((const long long*)eidx)[pos] : ((const int*)eidx)[pos];
}

// ---------------- 0) detect int64 vs int32 edge_index ----------------
__global__ void detect_idx_kernel(const unsigned* __restrict__ w) {
    __shared__ int any;
    if (threadIdx.x == 0) any = 0;
    __syncthreads();
    if (w[threadIdx.x * 2 + 1] != 0u) any = 1;
    __syncthreads();
    if (threadIdx.x == 0) g_is64 = (any == 0) ? 1 : 0;
}

// ---------------- 1) init ----------------
__global__ void init_kernel(const float* __restrict__ Wc, int NH, int Nn) {
    int i = blockIdx.x * blockDim.x + threadIdx.x;
    if (i < NH) g_s[i] = 0.0f;
    if (i < Nn) g_cnt[i] = 0;
    if (i < OUTD * OUTD) {
        int o = i >> 7, d = i & 127;
        g_WcT[d * OUTD + o] = Wc[i];
    }
}

// ---------------- 2) convert indices + histogram ----------------
__global__ void convert_hist_kernel(const void* __restrict__ eidx, int E) {
    int e = blockIdx.x * blockDim.x + threadIdx.x;
    if (e >= E) return;
    int is64 = g_is64;
    int nj = load_idx(eidx, is64, e);
    int ni = load_idx(eidx, is64, (long long)E + e);
    g_nj[e] = nj;
    g_ni[e] = ni;
    atomicAdd(&g_cnt[nj], 1);
}

// ---------------- 3) prep duplicated Wre ----------------
__global__ void prep_wdup_kernel(const float* __restrict__ Wre) {
    int idx = blockIdx.x * blockDim.x + threadIdx.x;  // 64*128
    if (idx >= EDIM * DDIM) return;
    int jj = idx >> 7, d = idx & 127;
    float v = Wre[d * EDIM + jj];
    g_wdup[jj * 128 + d] = make_float2(v, v);
}

// ---------------- 4a) fused node GEMM (q, k, silu-u) ----------------
#define PADW 132
#define PADA 36
__global__ __launch_bounds__(256)
void gemm3_kernel(const float* __restrict__ A,
                  const float* __restrict__ W0, const float* __restrict__ B0,
                  const float* __restrict__ W1p, const float* __restrict__ B1,
                  const float* __restrict__ W2p, const float* __restrict__ B2,
                  float* __restrict__ C0, float* __restrict__ C1, float* __restrict__ C2,
                  int M) {
    const float* W = (blockIdx.y == 0) ? W0 : (blockIdx.y == 1) ? W1p : W2p;
    const float* bias = (blockIdx.y == 0) ? B0 : (blockIdx.y == 1) ? B1 : B2;
    float* C = (blockIdx.y == 0) ? C0 : (blockIdx.y == 1) ? C1 : C2;
    int act = (blockIdx.y == 2);

    __shared__ float wsm[64 * PADW];
    __shared__ float asmv[64 * PADA];
    __shared__ float bsm[128];

    int tid = threadIdx.x;
    int row0 = blockIdx.x * 32;
    int nIdx = tid & 31, mIdx = tid >> 5;
    int n0 = nIdx * 4, m0 = mIdx * 4;
    if (tid < 128) bsm[tid] = bias[tid];

    unsigned long long acc2[4][2] = {};
    for (int kt = 0; kt < DDIM; kt += 64) {
        for (int idx = tid; idx < 128 * 64; idx += 256) {
            int o = idx >> 6, jj = idx & 63;
            wsm[jj * PADW + o] = W[o * DDIM + kt + jj];
        }
        for (int idx = tid; idx < 32 * 64; idx += 256) {
            int m = idx >> 6, jj = idx & 63;
            int r = row0 + m;
            asmv[jj * PADA + m] = (r < M) ? A[r * DDIM + kt + jj] : 0.0f;
        }
        __syncthreads();
        #pragma unroll 16
        for (int j = 0; j < 64; j++) {
            ulonglong2 wv = *(const ulonglong2*)&wsm[j * PADW + n0];
            float4 av = *(const float4*)&asmv[j * PADA + m0];
            unsigned long long a0 = pack2(av.x), a1 = pack2(av.y),
                               a2 = pack2(av.z), a3 = pack2(av.w);
            fma2(acc2[0][0], a0, wv.x); fma2(acc2[0][1], a0, wv.y);
            fma2(acc2[1][0], a1, wv.x); fma2(acc2[1][1], a1, wv.y);
            fma2(acc2[2][0], a2, wv.x); fma2(acc2[2][1], a2, wv.y);
            fma2(acc2[3][0], a3, wv.x); fma2(acc2[3][1], a3, wv.y);
        }
        __syncthreads();
    }
    #pragma unroll
    for (int mi = 0; mi < 4; mi++) {
        int r = row0 + m0 + mi;
        if (r < M) {
            float v0, v1, v2, v3;
            unpack2(acc2[mi][0], v0, v1);
            unpack2(acc2[mi][1], v2, v3);
            v0 += bsm[n0 + 0]; v1 += bsm[n0 + 1]; v2 += bsm[n0 + 2]; v3 += bsm[n0 + 3];
            if (act) { v0 = siluf(v0); v1 = siluf(v1); v2 = siluf(v2); v3 = siluf(v3); }
            *(float4*)&C[r * 128 + n0] = make_float4(v0, v1, v2, v3);
        }
    }
}

// ---------------- 4b) v = u @ W2^T + b2 ----------------
__global__ __launch_bounds__(256)
void gemm_kernel(const float* __restrict__ A, const float* __restrict__ W,
                 const float* __restrict__ bias, float* __restrict__ C, int M) {
    __shared__ float wsm[64 * PADW];
    __shared__ float asmv[64 * PADA];
    __shared__ float bsm[128];

    int tid = threadIdx.x;
    int row0 = blockIdx.x * 32;
    int nIdx = tid & 31, mIdx = tid >> 5;
    int n0 = nIdx * 4, m0 = mIdx * 4;
    if (tid < 128) bsm[tid] = bias[tid];

    unsigned long long acc2[4][2] = {};
    for (int kt = 0; kt < OUTD; kt += 64) {
        for (int idx = tid; idx < 128 * 64; idx += 256) {
            int o = idx >> 6, jj = idx & 63;
            wsm[jj * PADW + o] = W[o * OUTD + kt + jj];
        }
        for (int idx = tid; idx < 32 * 64; idx += 256) {
            int m = idx >> 6, jj = idx & 63;
            int r = row0 + m;
            asmv[jj * PADA + m] = (r < M) ? A[r * OUTD + kt + jj] : 0.0f;
        }
        __syncthreads();
        #pragma unroll 16
        for (int j = 0; j < 64; j++) {
            ulonglong2 wv = *(const ulonglong2*)&wsm[j * PADW + n0];
            float4 av = *(const float4*)&asmv[j * PADA + m0];
            unsigned long long a0 = pack2(av.x), a1 = pack2(av.y),
                               a2 = pack2(av.z), a3 = pack2(av.w);
            fma2(acc2[0][0], a0, wv.x); fma2(acc2[0][1], a0, wv.y);
            fma2(acc2[1][0], a1, wv.x); fma2(acc2[1][1], a1, wv.y);
            fma2(acc2[2][0], a2, wv.x); fma2(acc2[2][1], a2, wv.y);
            fma2(acc2[3][0], a3, wv.x); fma2(acc2[3][1], a3, wv.y);
        }
        __syncthreads();
    }
    #pragma unroll
    for (int mi = 0; mi < 4; mi++) {
        int r = row0 + m0 + mi;
        if (r < M) {
            float v0, v1, v2, v3;
            unpack2(acc2[mi][0], v0, v1);
            unpack2(acc2[mi][1], v2, v3);
            v0 += bsm[n0 + 0]; v1 += bsm[n0 + 1]; v2 += bsm[n0 + 2]; v3 += bsm[n0 + 3];
            *(float4*)&C[r * 128 + n0] = make_float4(v0, v1, v2, v3);
        }
    }
}

// ---------------- 5) sort: scan + scatter ----------------
__global__ __launch_bounds__(1024)
void scan_kernel(int Nn) {
    __shared__ int part[1024];
    int t = threadIdx.x;
    int chunk = (Nn + 1023) >> 10;
    int base = t * chunk;
    int local[16];
    int sum = 0;
    for (int i = 0; i < chunk; i++) {
        int idx = base + i;
        int c = (idx < Nn) ? g_cnt[idx] : 0;
        local[i] = sum; sum += c;
    }
    part[t] = sum;
    __syncthreads();
    for (int off = 1; off < 1024; off <<= 1) {
        int v = (t >= off) ? part[t - off] : 0;
        __syncthreads();
        part[t] += v;
        __syncthreads();
    }
    int pre = (t > 0) ? part[t - 1] : 0;
    for (int i = 0; i < chunk; i++) {
        int idx = base + i;
        if (idx < Nn) { int s0 = pre + local[i]; g_start[idx] = s0; g_off[idx] = s0; }
    }
    if (t == 0) g_start[Nn] = part[1023];
}

__global__ void scatter_kernel(int E) {
    int e = blockIdx.x * blockDim.x + threadIdx.x;
    if (e >= E) return;
    int nj = g_nj[e];
    int ni = g_ni[e];
    int pos = atomicAdd(&g_off[nj], 1);
    g_elist[pos] = e;
    g_njs[pos] = nj;
    g_nis[pos] = ni;
}

// ---------------- 6) edge logits (sorted order): re GEMM + q*k dot + exp + segment sum ----------------
// 128 edges/block (sorted positions), 256 threads. K chunked by 16, Wre pre-duplicated.
#define ELB 128
#define KC 16
__global__ __launch_bounds__(256, 2)
void edge_logits_kernel(const float* __restrict__ T, const float* __restrict__ bre, int E) {
    __shared__ float2 wdsm[KC * 128];     // wdsm[jj][d] = {w,w}          16KB
    __shared__ float  tsm[KC * 132];      // tsm[jj][eLocal]              8.4KB
    __shared__ float  bsm[128];
    __shared__ int    elsm[ELB];

    int tid = threadIdx.x;
    int warp = tid >> 5, lane = tid & 31;
    int eBase = blockIdx.x * ELB;
    if (tid < 128) bsm[tid] = bre[tid];
    if (tid < ELB) elsm[tid] = (eBase + tid < E) ? g_elist[eBase + tid] : 0;
    __syncthreads();

    int d0 = lane * 4;
    unsigned long long acc[8][4] = {};    // [edge-pair][d]  (pair packs edges 2p,2p+1)

    for (int kc = 0; kc < EDIM / KC; kc++) {
        // stage wdup chunk: KC*128 float2 = 1024 float4
        {
            const float4* src = (const float4*)(g_wdup + kc * KC * 128);
            float4* dst = (float4*)wdsm;
            #pragma unroll
            for (int i = 0; i < 4; i++) dst[tid + i * 256] = src[tid + i * 256];
        }
        // stage t chunk (gathered via sorted edge list), transposed [jj][e]
        for (int idx = tid; idx < ELB * KC; idx += 256) {
            int jj = idx & (KC - 1), eL = idx >> 4;
            int ge = elsm[eL];
            float tv = (eBase + eL < E) ? T[(long long)ge * EDIM + kc * KC + jj] : 0.0f;
            tsm[jj * 132 + eL] = tv;
        }
        __syncthreads();
        #pragma unroll
        for (int j = 0; j < KC; j++) {
            ulonglong2 w01 = *(const ulonglong2*)&wdsm[j * 128 + d0];
            ulonglong2 w23 = *(const ulonglong2*)&wdsm[j * 128 + d0 + 2];
            const ulonglong2* tp = (const ulonglong2*)&tsm[j * 132 + warp * 16];
            ulonglong2 tA = tp[0], tB = tp[1], tC = tp[2], tD = tp[3];
            fma2(acc[0][0], tA.x, w01.x); fma2(acc[0][1], tA.x, w01.y); fma2(acc[0][2], tA.x, w23.x); fma2(acc[0][3], tA.x, w23.y);
            fma2(acc[1][0], tA.y, w01.x); fma2(acc[1][1], tA.y, w01.y); fma2(acc[1][2], tA.y, w23.x); fma2(acc[1][3], tA.y, w23.y);
            fma2(acc[2][0], tB.x, w01.x); fma2(acc[2][1], tB.x, w01.y); fma2(acc[2][2], tB.x, w23.x); fma2(acc[2][3], tB.x, w23.y);
            fma2(acc[3][0], tB.y, w01.x); fma2(acc[3][1], tB.y, w01.y); fma2(acc[3][2], tB.y, w23.x); fma2(acc[3][3], tB.y, w23.y);
            fma2(acc[4][0], tC.x, w01.x); fma2(acc[4][1], tC.x, w01.y); fma2(acc[4][2], tC.x, w23.x); fma2(acc[4][3], tC.x, w23.y);
            fma2(acc[5][0], tC.y, w01.x); fma2(acc[5][1], tC.y, w01.y); fma2(acc[5][2], tC.y, w23.x); fma2(acc[5][3], tC.y, w23.y);
            fma2(acc[6][0], tD.x, w01.x); fma2(acc[6][1], tD.x, w01.y); fma2(acc[6][2], tD.x, w23.x); fma2(acc[6][3], tD.x, w23.y);
            fma2(acc[7][0], tD.y, w01.x); fma2(acc[7][1], tD.y, w01.y); fma2(acc[7][2], tD.y, w23.x); fma2(acc[7][3], tD.y, w23.y);
        }
        __syncthreads();
    }

    int head = lane >> 2;
    float b0 = bsm[d0 + 0], b1 = bsm[d0 + 1], b2 = bsm[d0 + 2], b3 = bsm[d0 + 3];

    #pragma unroll
    for (int ei = 0; ei < 16; ei++) {
        int iPos = eBase + warp * 16 + ei;    // uniform within warp
        if (iPos >= E) continue;
        int ni = g_nis[iPos];
        int nj = g_njs[iPos];
        float4 q4 = *(const float4*)&g_q[ni * 128 + d0];
        float4 k4 = *(const float4*)&g_k[nj * 128 + d0];
        int p = ei >> 1;
        float lo0, hi0, lo1, hi1, lo2, hi2, lo3, hi3;
        unpack2(acc[p][0], lo0, hi0);
        unpack2(acc[p][1], lo1, hi1);
        unpack2(acc[p][2], lo2, hi2);
        unpack2(acc[p][3], lo3, hi3);
        float x0 = (ei & 1) ? hi0 : lo0;
        float x1 = (ei & 1) ? hi1 : lo1;
        float x2 = (ei & 1) ? hi2 : lo2;
        float x3 = (ei & 1) ? hi3 : lo3;
        x0 = siluf(x0 + b0); x1 = siluf(x1 + b1);
        x2 = siluf(x2 + b2); x3 = siluf(x3 + b3);
        float part = x0 * q4.x * k4.x + x1 * q4.y * k4.y
                   + x2 * q4.z * k4.z + x3 * q4.w * k4.w;
        part += __shfl_xor_sync(0xffffffffu, part, 1);
        part += __shfl_xor_sync(0xffffffffu, part, 2);
        if ((lane & 3) == 0) {
            float ex = __expf(fminf(part, 80.0f));  // shift-free softmax (logits bounded)
            g_a[iPos * 8 + head] = ex;
            atomicAdd(&g_s[ni * 8 + head], ex);
        }
    }
}

// ---------------- 7) invert sums ----------------
__global__ void sinv_kernel(int NH) {
    int i = blockIdx.x * blockDim.x + threadIdx.x;
    if (i < NH) g_s[i] = 0.25f / (g_s[i] + 1e-16f);
}

// ---------------- 8) per-node P ----------------
__global__ __launch_bounds__(256)
void pmat_kernel(int Nn) {
    int tid = threadIdx.x;
    int h = tid >> 5;
    int o0 = (tid & 31) * 4;
    int n0 = blockIdx.x * 8;

    float acc[8][4];
    #pragma unroll
    for (int n = 0; n < 8; n++) { acc[n][0] = acc[n][1] = acc[n][2] = acc[n][3] = 0.0f; }

    #pragma unroll
    for (int dd = 0; dd < 16; dd++) {
        int d = h * 16 + dd;
        float4 w4 = *(const float4*)&g_WcT[d * OUTD + o0];
        #pragma unroll
        for (int n = 0; n < 8; n++) {
            int r = n0 + n;
            float vv = (r < Nn) ? g_v[r * OUTD + d] : 0.0f;
            acc[n][0] = fmaf(vv, w4.x, acc[n][0]);
            acc[n][1] = fmaf(vv, w4.y, acc[n][1]);
            acc[n][2] = fmaf(vv, w4.z, acc[n][2]);
            acc[n][3] = fmaf(vv, w4.w, acc[n][3]);
        }
    }
    #pragma unroll
    for (int n = 0; n < 8; n++) {
        int r = n0 + n;
        if (r < Nn) {
            *(float4*)&g_P[((r * 8 + h) * OUTD) + o0] =
                make_float4(acc[n][0], acc[n][1], acc[n][2], acc[n][3]);
        }
    }
}

// ---------------- 9) output ----------------
__global__ __launch_bounds__(256)
void out_kernel(const float* __restrict__ bc, float* __restrict__ outp, int E) {
    int n = blockIdx.x;
    int start = g_start[n], end = g_start[n + 1];
    if (start == end) return;
    int warp = threadIdx.x >> 5, lane = threadIdx.x & 31;
    int o0 = lane * 4;

    float4 P4[8];
    #pragma unroll
    for (int h = 0; h < 8; h++)
        P4[h] = *(const float4*)&g_P[((n * 8 + h) * OUTD) + o0];
    float4 bc4 = *(const float4*)&bc[o0];

    for (int i = start + warp; i < end; i += 8) {
        int e = g_elist[i];
        float w = 0.0f;
        if (lane < 8) {
            int ni = g_nis[i];
            w = g_a[i * 8 + lane] * g_s[ni * 8 + lane];
        }
        float4 acc = bc4;
        #pragma unroll
        for (int h = 0; h < 8; h++) {
            float wh = __shfl_sync(0xffffffffu, w, h);
            acc.x = fmaf(wh, P4[h].x, acc.x);
            acc.y = fmaf(wh, P4[h].y, acc.y);
            acc.z = fmaf(wh, P4[h].z, acc.z);
            acc.w = fmaf(wh, P4[h].w, acc.w);
        }
        *(float4*)&outp[(long long)e * 128 + o0] = acc;
    }
}

// ---------------- host launcher ----------------
extern "C" void kernel_launch(void* const* d_in, const int* in_sizes, int n_in,
                              void* d_out, int out_size) {
    const float* h    = (const float*)d_in[0];
    const float* tij  = (const float*)d_in[1];
    const void*  eidx = d_in[2];
    const float* Wq   = (const float*)d_in[3];
    const float* bq   = (const float*)d_in[4];
    const float* Wk   = (const float*)d_in[5];
    const float* bk   = (const float*)d_in[6];
    const float* W1   = (const float*)d_in[7];
    const float* b1   = (const float*)d_in[8];
    const float* W2   = (const float*)d_in[9];
    const float* b2   = (const float*)d_in[10];
    const float* Wre  = (const float*)d_in[11];
    const float* bre  = (const float*)d_in[12];
    const float* Wc   = (const float*)d_in[13];
    const float* bc   = (const float*)d_in[14];

    int Nn = in_sizes[0] / DDIM;     // 10000
    int E  = in_sizes[1] / EDIM;     // 640000

    float *pq, *pk, *pu, *pv;
    cudaGetSymbolAddress((void**)&pq, g_q);
    cudaGetSymbolAddress((void**)&pk, g_k);
    cudaGetSymbolAddress((void**)&pu, g_u);
    cudaGetSymbolAddress((void**)&pv, g_v);

    // 0) detect index width
    detect_idx_kernel<<<1, 1024>>>((const unsigned*)eidx);

    // 1) init
    {
        int total = Nn * HDS;
        if (total < OUTD * OUTD) total = OUTD * OUTD;
        if (total < Nn) total = Nn;
        init_kernel<<<(total + 255) / 256, 256>>>(Wc, Nn * HDS, Nn);
    }

    // 2) convert indices + histogram; 3) prep duplicated Wre
    convert_hist_kernel<<<(E + 255) / 256, 256>>>(eidx, E);
    prep_wdup_kernel<<<(EDIM * DDIM + 255) / 256, 256>>>(Wre);

    // 4) node projections
    int gb = (Nn + 31) / 32;
    {
        dim3 grid(gb, 3);
        gemm3_kernel<<<grid, 256>>>(h, Wq, bq, Wk, bk, W1, b1, pq, pk, pu, Nn);
    }
    gemm_kernel<<<gb, 256>>>(pu, W2, b2, pv, Nn);

    // 5) sort by nj
    scan_kernel<<<1, 1024>>>(Nn);
    scatter_kernel<<<(E + 255) / 256, 256>>>(E);

    // 6) edge logits + exp + segment sum (sorted order)
    edge_logits_kernel<<<(E + ELB - 1) / ELB, 256>>>(tij, bre, E);

    // 7) invert sums
    sinv_kernel<<<(Nn * HDS + 255) / 256, 256>>>(Nn * HDS);

    // 8) P matrix
    pmat_kernel<<<(Nn + 7) / 8, 256>>>(Nn);

    // 9) output
    out_kernel<<<Nn, 256>>>(bc, (float*)d_out, E);
}

// round 6
// speedup vs baseline: 1.2350x; 1.2350x over previous
#include <cuda_runtime.h>
#include <cstdint>

// ---------------- problem constants ----------------
#define NMAX 10000
#define EMAX 640000
#define DDIM 128
#define EDIM 64
#define HDS  8
#define OUTD 128

// ---------------- device scratch ----------------
__device__ __align__(16) float g_q[NMAX * DDIM];
__device__ __align__(16) float g_k[NMAX * DDIM];
__device__ __align__(16) float g_u[NMAX * OUTD];
__device__ __align__(16) float g_v[NMAX * OUTD];
__device__ __align__(16) float g_P[NMAX * HDS * OUTD];
__device__ __align__(16) float g_a[EMAX * HDS];     // exp(logit), by ORIGINAL edge id
__device__ __align__(16) float g_s[NMAX * HDS];     // segment sums -> 0.25/(s+eps)
__device__ __align__(16) float g_WcT[OUTD * OUTD];
__device__ __align__(16) float2 g_wdup[EDIM * DDIM]; // wdup[jj][d] = {Wre[d][jj], Wre[d][jj]}
__device__ int g_is64;
__device__ int g_nj[EMAX];
__device__ int g_ni[EMAX];
__device__ int g_cnt[NMAX];
__device__ int g_start[NMAX + 1];
__device__ int g_off[NMAX];
__device__ int g_elist[EMAX];

// ---------------- helpers ----------------
__device__ __forceinline__ unsigned long long pack2(float x) {
    unsigned long long r; unsigned u = __float_as_uint(x);
    asm("mov.b64 %0, {%1, %1};" : "=l"(r) : "r"(u));
    return r;
}
__device__ __forceinline__ void fma2(unsigned long long& d, unsigned long long a, unsigned long long b) {
    asm("fma.rn.f32x2 %0, %1, %2, %0;" : "+l"(d) : "l"(a), "l"(b));
}
__device__ __forceinline__ void unpack2(unsigned long long v, float& x, float& y) {
    unsigned a, b;
    asm("mov.b64 {%0, %1}, %2;" : "=r"(a), "=r"(b) : "l"(v));
    x = __uint_as_float(a); y = __uint_as_float(b);
}
__device__ __forceinline__ float siluf(float x) { return x / (1.0f + __expf(-x)); }
__device__ __forceinline__ int load_idx(const void* eidx, int is64, long long pos) {
    return is64 ? (int)((const long long*)eidx)[pos] : ((const int*)eidx)[pos];
}

// ---------------- 0) detect int64 vs int32 edge_index ----------------
__global__ void detect_idx_kernel(const unsigned* __restrict__ w) {
    __shared__ int any;
    if (threadIdx.x == 0) any = 0;
    __syncthreads();
    if (w[threadIdx.x * 2 + 1] != 0u) any = 1;
    __syncthreads();
    if (threadIdx.x == 0) g_is64 = (any == 0) ? 1 : 0;
}

// ---------------- 1) init ----------------
__global__ void init_kernel(const float* __restrict__ Wc, int NH, int Nn) {
    int i = blockIdx.x * blockDim.x + threadIdx.x;
    if (i < NH) g_s[i] = 0.0f;
    if (i < Nn) g_cnt[i] = 0;
    if (i < OUTD * OUTD) {
        int o = i >> 7, d = i & 127;
        g_WcT[d * OUTD + o] = Wc[i];
    }
}

// ---------------- 2) convert indices + histogram ----------------
__global__ void convert_hist_kernel(const void* __restrict__ eidx, int E) {
    int e = blockIdx.x * blockDim.x + threadIdx.x;
    if (e >= E) return;
    int is64 = g_is64;
    int nj = load_idx(eidx, is64, e);
    int ni = load_idx(eidx, is64, (long long)E + e);
    g_nj[e] = nj;
    g_ni[e] = ni;
    atomicAdd(&g_cnt[nj], 1);
}

// ---------------- 3) prep duplicated Wre ----------------
__global__ void prep_wdup_kernel(const float* __restrict__ Wre) {
    int idx = blockIdx.x * blockDim.x + threadIdx.x;  // 64*128
    if (idx >= EDIM * DDIM) return;
    int jj = idx >> 7, d = idx & 127;
    float v = Wre[d * EDIM + jj];
    g_wdup[jj * 128 + d] = make_float2(v, v);
}

// ---------------- 4a) fused node GEMM (q, k, silu-u) ----------------
#define PADW 132
#define PADA 36
__global__ __launch_bounds__(256)
void gemm3_kernel(const float* __restrict__ A,
                  const float* __restrict__ W0, const float* __restrict__ B0,
                  const float* __restrict__ W1p, const float* __restrict__ B1,
                  const float* __restrict__ W2p, const float* __restrict__ B2,
                  float* __restrict__ C0, float* __restrict__ C1, float* __restrict__ C2,
                  int M) {
    const float* W = (blockIdx.y == 0) ? W0 : (blockIdx.y == 1) ? W1p : W2p;
    const float* bias = (blockIdx.y == 0) ? B0 : (blockIdx.y == 1) ? B1 : B2;
    float* C = (blockIdx.y == 0) ? C0 : (blockIdx.y == 1) ? C1 : C2;
    int act = (blockIdx.y == 2);

    __shared__ float wsm[64 * PADW];
    __shared__ float asmv[64 * PADA];
    __shared__ float bsm[128];

    int tid = threadIdx.x;
    int row0 = blockIdx.x * 32;
    int nIdx = tid & 31, mIdx = tid >> 5;
    int n0 = nIdx * 4, m0 = mIdx * 4;
    if (tid < 128) bsm[tid] = bias[tid];

    unsigned long long acc2[4][2] = {};
    for (int kt = 0; kt < DDIM; kt += 64) {
        for (int idx = tid; idx < 128 * 64; idx += 256) {
            int o = idx >> 6, jj = idx & 63;
            wsm[jj * PADW + o] = W[o * DDIM + kt + jj];
        }
        for (int idx = tid; idx < 32 * 64; idx += 256) {
            int m = idx >> 6, jj = idx & 63;
            int r = row0 + m;
            asmv[jj * PADA + m] = (r < M) ? A[r * DDIM + kt + jj] : 0.0f;
        }
        __syncthreads();
        #pragma unroll 16
        for (int j = 0; j < 64; j++) {
            ulonglong2 wv = *(const ulonglong2*)&wsm[j * PADW + n0];
            float4 av = *(const float4*)&asmv[j * PADA + m0];
            unsigned long long a0 = pack2(av.x), a1 = pack2(av.y),
                               a2 = pack2(av.z), a3 = pack2(av.w);
            fma2(acc2[0][0], a0, wv.x); fma2(acc2[0][1], a0, wv.y);
            fma2(acc2[1][0], a1, wv.x); fma2(acc2[1][1], a1, wv.y);
            fma2(acc2[2][0], a2, wv.x); fma2(acc2[2][1], a2, wv.y);
            fma2(acc2[3][0], a3, wv.x); fma2(acc2[3][1], a3, wv.y);
        }
        __syncthreads();
    }
    #pragma unroll
    for (int mi = 0; mi < 4; mi++) {
        int r = row0 + m0 + mi;
        if (r < M) {
            float v0, v1, v2, v3;
            unpack2(acc2[mi][0], v0, v1);
            unpack2(acc2[mi][1], v2, v3);
            v0 += bsm[n0 + 0]; v1 += bsm[n0 + 1]; v2 += bsm[n0 + 2]; v3 += bsm[n0 + 3];
            if (act) { v0 = siluf(v0); v1 = siluf(v1); v2 = siluf(v2); v3 = siluf(v3); }
            *(float4*)&C[r * 128 + n0] = make_float4(v0, v1, v2, v3);
        }
    }
}

// ---------------- 4b) v = u @ W2^T + b2 ----------------
__global__ __launch_bounds__(256)
void gemm_kernel(const float* __restrict__ A, const float* __restrict__ W,
                 const float* __restrict__ bias, float* __restrict__ C, int M) {
    __shared__ float wsm[64 * PADW];
    __shared__ float asmv[64 * PADA];
    __shared__ float bsm[128];

    int tid = threadIdx.x;
    int row0 = blockIdx.x * 32;
    int nIdx = tid & 31, mIdx = tid >> 5;
    int n0 = nIdx * 4, m0 = mIdx * 4;
    if (tid < 128) bsm[tid] = bias[tid];

    unsigned long long acc2[4][2] = {};
    for (int kt = 0; kt < OUTD; kt += 64) {
        for (int idx = tid; idx < 128 * 64; idx += 256) {
            int o = idx >> 6, jj = idx & 63;
            wsm[jj * PADW + o] = W[o * OUTD + kt + jj];
        }
        for (int idx = tid; idx < 32 * 64; idx += 256) {
            int m = idx >> 6, jj = idx & 63;
            int r = row0 + m;
            asmv[jj * PADA + m] = (r < M) ? A[r * OUTD + kt + jj] : 0.0f;
        }
        __syncthreads();
        #pragma unroll 16
        for (int j = 0; j < 64; j++) {
            ulonglong2 wv = *(const ulonglong2*)&wsm[j * PADW + n0];
            float4 av = *(const float4*)&asmv[j * PADA + m0];
            unsigned long long a0 = pack2(av.x), a1 = pack2(av.y),
                               a2 = pack2(av.z), a3 = pack2(av.w);
            fma2(acc2[0][0], a0, wv.x); fma2(acc2[0][1], a0, wv.y);
            fma2(acc2[1][0], a1, wv.x); fma2(acc2[1][1], a1, wv.y);
            fma2(acc2[2][0], a2, wv.x); fma2(acc2[2][1], a2, wv.y);
            fma2(acc2[3][0], a3, wv.x); fma2(acc2[3][1], a3, wv.y);
        }
        __syncthreads();
    }
    #pragma unroll
    for (int mi = 0; mi < 4; mi++) {
        int r = row0 + m0 + mi;
        if (r < M) {
            float v0, v1, v2, v3;
            unpack2(acc2[mi][0], v0, v1);
            unpack2(acc2[mi][1], v2, v3);
            v0 += bsm[n0 + 0]; v1 += bsm[n0 + 1]; v2 += bsm[n0 + 2]; v3 += bsm[n0 + 3];
            *(float4*)&C[r * 128 + n0] = make_float4(v0, v1, v2, v3);
        }
    }
}

// ---------------- 5) sort: scan + scatter ----------------
__global__ __launch_bounds__(1024)
void scan_kernel(int Nn) {
    __shared__ int part[1024];
    int t = threadIdx.x;
    int chunk = (Nn + 1023) >> 10;
    int base = t * chunk;
    int local[16];
    int sum = 0;
    for (int i = 0; i < chunk; i++) {
        int idx = base + i;
        int c = (idx < Nn) ? g_cnt[idx] : 0;
        local[i] = sum; sum += c;
    }
    part[t] = sum;
    __syncthreads();
    for (int off = 1; off < 1024; off <<= 1) {
        int v = (t >= off) ? part[t - off] : 0;
        __syncthreads();
        part[t] += v;
        __syncthreads();
    }
    int pre = (t > 0) ? part[t - 1] : 0;
    for (int i = 0; i < chunk; i++) {
        int idx = base + i;
        if (idx < Nn) { int s0 = pre + local[i]; g_start[idx] = s0; g_off[idx] = s0; }
    }
    if (t == 0) g_start[Nn] = part[1023];
}

__global__ void scatter_kernel(int E) {
    int e = blockIdx.x * blockDim.x + threadIdx.x;
    if (e >= E) return;
    int nj = g_nj[e];
    int pos = atomicAdd(&g_off[nj], 1);
    g_elist[pos] = e;
}

// ---------------- 6) edge logits (NATURAL order): re GEMM + q*k dot + exp + segment sum ----------------
// 128 edges/block, 256 threads, K chunked by 16. Packed operand = edge pairs straight
// from smem (zero pack-movs); Wre pre-duplicated {w,w} in g_wdup.
#define ELB 128
#define KC 16
__global__ __launch_bounds__(256, 2)
void edge_logits_kernel(const float* __restrict__ T, const float* __restrict__ bre, int E) {
    __shared__ float2 wdsm[KC * 128];     // wdsm[jj][d] = {w,w}   16KB
    __shared__ float  tsm[KC * 132];      // tsm[jj][eLocal]       8.4KB
    __shared__ float  bsm[128];

    int tid = threadIdx.x;
    int warp = tid >> 5, lane = tid & 31;
    int eBase = blockIdx.x * ELB;
    if (tid < 128) bsm[tid] = bre[tid];

    int d0 = lane * 4;
    unsigned long long acc[8][4] = {};    // [edge-pair][d] ; pair p = local edges (2p, 2p+1)

    for (int kc = 0; kc < EDIM / KC; kc++) {
        // stage duplicated Wre chunk: KC*128 float2 = 1024 float4
        {
            const float4* src = (const float4*)(g_wdup + kc * KC * 128);
            float4* dst = (float4*)wdsm;
            #pragma unroll
            for (int i = 0; i < 4; i++) dst[tid + i * 256] = src[tid + i * 256];
        }
        // stage t chunk, natural order (coalesced), transposed [jj][e]
        for (int idx = tid; idx < ELB * KC; idx += 256) {
            int jj = idx & (KC - 1), eL = idx >> 4;
            int e = eBase + eL;
            tsm[jj * 132 + eL] = (e < E) ? T[(long long)e * EDIM + kc * KC + jj] : 0.0f;
        }
        __syncthreads();
        #pragma unroll
        for (int j = 0; j < KC; j++) {
            ulonglong2 w01 = *(const ulonglong2*)&wdsm[j * 128 + d0];
            ulonglong2 w23 = *(const ulonglong2*)&wdsm[j * 128 + d0 + 2];
            const ulonglong2* tp = (const ulonglong2*)&tsm[j * 132 + warp * 16];
            ulonglong2 tA = tp[0], tB = tp[1], tC = tp[2], tD = tp[3];   // warp-uniform broadcasts
            fma2(acc[0][0], tA.x, w01.x); fma2(acc[0][1], tA.x, w01.y); fma2(acc[0][2], tA.x, w23.x); fma2(acc[0][3], tA.x, w23.y);
            fma2(acc[1][0], tA.y, w01.x); fma2(acc[1][1], tA.y, w01.y); fma2(acc[1][2], tA.y, w23.x); fma2(acc[1][3], tA.y, w23.y);
            fma2(acc[2][0], tB.x, w01.x); fma2(acc[2][1], tB.x, w01.y); fma2(acc[2][2], tB.x, w23.x); fma2(acc[2][3], tB.x, w23.y);
            fma2(acc[3][0], tB.y, w01.x); fma2(acc[3][1], tB.y, w01.y); fma2(acc[3][2], tB.y, w23.x); fma2(acc[3][3], tB.y, w23.y);
            fma2(acc[4][0], tC.x, w01.x); fma2(acc[4][1], tC.x, w01.y); fma2(acc[4][2], tC.x, w23.x); fma2(acc[4][3], tC.x, w23.y);
            fma2(acc[5][0], tC.y, w01.x); fma2(acc[5][1], tC.y, w01.y); fma2(acc[5][2], tC.y, w23.x); fma2(acc[5][3], tC.y, w23.y);
            fma2(acc[6][0], tD.x, w01.x); fma2(acc[6][1], tD.x, w01.y); fma2(acc[6][2], tD.x, w23.x); fma2(acc[6][3], tD.x, w23.y);
            fma2(acc[7][0], tD.y, w01.x); fma2(acc[7][1], tD.y, w01.y); fma2(acc[7][2], tD.y, w23.x); fma2(acc[7][3], tD.y, w23.y);
        }
        __syncthreads();
    }

    int head = lane >> 2;
    float b0 = bsm[d0 + 0], b1 = bsm[d0 + 1], b2 = bsm[d0 + 2], b3 = bsm[d0 + 3];

    #pragma unroll
    for (int ei = 0; ei < 16; ei++) {
        int e = eBase + warp * 16 + ei;   // uniform within warp
        if (e >= E) continue;
        int nj = g_nj[e];
        int ni = g_ni[e];
        float4 q4 = *(const float4*)&g_q[ni * 128 + d0];
        float4 k4 = *(const float4*)&g_k[nj * 128 + d0];
        int p = ei >> 1;
        float lo0, hi0, lo1, hi1, lo2, hi2, lo3, hi3;
        unpack2(acc[p][0], lo0, hi0);
        unpack2(acc[p][1], lo1, hi1);
        unpack2(acc[p][2], lo2, hi2);
        unpack2(acc[p][3], lo3, hi3);
        float x0 = (ei & 1) ? hi0 : lo0;
        float x1 = (ei & 1) ? hi1 : lo1;
        float x2 = (ei & 1) ? hi2 : lo2;
        float x3 = (ei & 1) ? hi3 : lo3;
        x0 = siluf(x0 + b0); x1 = siluf(x1 + b1);
        x2 = siluf(x2 + b2); x3 = siluf(x3 + b3);
        float part = x0 * q4.x * k4.x + x1 * q4.y * k4.y
                   + x2 * q4.z * k4.z + x3 * q4.w * k4.w;
        part += __shfl_xor_sync(0xffffffffu, part, 1);
        part += __shfl_xor_sync(0xffffffffu, part, 2);
        if ((lane & 3) == 0) {
            float ex = __expf(fminf(part, 80.0f));  // shift-free softmax (logits bounded)
            g_a[e * 8 + head] = ex;
            atomicAdd(&g_s[ni * 8 + head], ex);
        }
    }
}

// ---------------- 7) invert sums ----------------
__global__ void sinv_kernel(int NH) {
    int i = blockIdx.x * blockDim.x + threadIdx.x;
    if (i < NH) g_s[i] = 0.25f / (g_s[i] + 1e-16f);
}

// ---------------- 8) per-node P ----------------
__global__ __launch_bounds__(256)
void pmat_kernel(int Nn) {
    int tid = threadIdx.x;
    int h = tid >> 5;
    int o0 = (tid & 31) * 4;
    int n0 = blockIdx.x * 8;

    float acc[8][4];
    #pragma unroll
    for (int n = 0; n < 8; n++) { acc[n][0] = acc[n][1] = acc[n][2] = acc[n][3] = 0.0f; }

    #pragma unroll
    for (int dd = 0; dd < 16; dd++) {
        int d = h * 16 + dd;
        float4 w4 = *(const float4*)&g_WcT[d * OUTD + o0];
        #pragma unroll
        for (int n = 0; n < 8; n++) {
            int r = n0 + n;
            float vv = (r < Nn) ? g_v[r * OUTD + d] : 0.0f;
            acc[n][0] = fmaf(vv, w4.x, acc[n][0]);
            acc[n][1] = fmaf(vv, w4.y, acc[n][1]);
            acc[n][2] = fmaf(vv, w4.z, acc[n][2]);
            acc[n][3] = fmaf(vv, w4.w, acc[n][3]);
        }
    }
    #pragma unroll
    for (int n = 0; n < 8; n++) {
        int r = n0 + n;
        if (r < Nn) {
            *(float4*)&g_P[((r * 8 + h) * OUTD) + o0] =
                make_float4(acc[n][0], acc[n][1], acc[n][2], acc[n][3]);
        }
    }
}

// ---------------- 9) output: block per node nj, P slice in registers ----------------
__global__ __launch_bounds__(256)
void out_kernel(const float* __restrict__ bc, float* __restrict__ outp, int E) {
    int n = blockIdx.x;
    int start = g_start[n], end = g_start[n + 1];
    if (start == end) return;
    int warp = threadIdx.x >> 5, lane = threadIdx.x & 31;
    int o0 = lane * 4;

    float4 P4[8];
    #pragma unroll
    for (int h = 0; h < 8; h++)
        P4[h] = *(const float4*)&g_P[((n * 8 + h) * OUTD) + o0];
    float4 bc4 = *(const float4*)&bc[o0];

    for (int i = start + warp; i < end; i += 8) {
        int e = g_elist[i];
        float w = 0.0f;
        if (lane < 8) {
            int ni = g_ni[e];
            w = g_a[e * 8 + lane] * g_s[ni * 8 + lane];   // g_s holds 0.25/(s+eps)
        }
        float4 acc = bc4;
        #pragma unroll
        for (int h = 0; h < 8; h++) {
            float wh = __shfl_sync(0xffffffffu, w, h);
            acc.x = fmaf(wh, P4[h].x, acc.x);
            acc.y = fmaf(wh, P4[h].y, acc.y);
            acc.z = fmaf(wh, P4[h].z, acc.z);
            acc.w = fmaf(wh, P4[h].w, acc.w);
        }
        *(float4*)&outp[(long long)e * 128 + o0] = acc;
    }
}

// ---------------- host launcher ----------------
extern "C" void kernel_launch(void* const* d_in, const int* in_sizes, int n_in,
                              void* d_out, int out_size) {
    const float* h    = (const float*)d_in[0];
    const float* tij  = (const float*)d_in[1];
    const void*  eidx = d_in[2];
    const float* Wq   = (const float*)d_in[3];
    const float* bq   = (const float*)d_in[4];
    const float* Wk   = (const float*)d_in[5];
    const float* bk   = (const float*)d_in[6];
    const float* W1   = (const float*)d_in[7];
    const float* b1   = (const float*)d_in[8];
    const float* W2   = (const float*)d_in[9];
    const float* b2   = (const float*)d_in[10];
    const float* Wre  = (const float*)d_in[11];
    const float* bre  = (const float*)d_in[12];
    const float* Wc   = (const float*)d_in[13];
    const float* bc   = (const float*)d_in[14];

    int Nn = in_sizes[0] / DDIM;     // 10000
    int E  = in_sizes[1] / EDIM;     // 640000

    float *pq, *pk, *pu, *pv;
    cudaGetSymbolAddress((void**)&pq, g_q);
    cudaGetSymbolAddress((void**)&pk, g_k);
    cudaGetSymbolAddress((void**)&pu, g_u);
    cudaGetSymbolAddress((void**)&pv, g_v);

    // 0) detect index width
    detect_idx_kernel<<<1, 1024>>>((const unsigned*)eidx);

    // 1) init
    {
        int total = Nn * HDS;
        if (total < OUTD * OUTD) total = OUTD * OUTD;
        if (total < Nn) total = Nn;
        init_kernel<<<(total + 255) / 256, 256>>>(Wc, Nn * HDS, Nn);
    }

    // 2) convert indices + histogram; 3) prep duplicated Wre
    convert_hist_kernel<<<(E + 255) / 256, 256>>>(eidx, E);
    prep_wdup_kernel<<<(EDIM * DDIM + 255) / 256, 256>>>(Wre);

    // 4) node projections
    int gb = (Nn + 31) / 32;
    {
        dim3 grid(gb, 3);
        gemm3_kernel<<<grid, 256>>>(h, Wq, bq, Wk, bk, W1, b1, pq, pk, pu, Nn);
    }
    gemm_kernel<<<gb, 256>>>(pu, W2, b2, pv, Nn);

    // 5) sort by nj (for out_kernel locality only)
    scan_kernel<<<1, 1024>>>(Nn);
    scatter_kernel<<<(E + 255) / 256, 256>>>(E);

    // 6) edge logits + exp + segment sum (natural order, coalesced T)
    edge_logits_kernel<<<(E + ELB - 1) / ELB, 256>>>(tij, bre, E);

    // 7) invert sums
    sinv_kernel<<<(Nn * HDS + 255) / 256, 256>>>(Nn * HDS);

    // 8) P matrix
    pmat_kernel<<<(Nn + 7) / 8, 256>>>(Nn);

    // 9) output
    out_kernel<<<Nn, 256>>>(bc, (float*)d_out, E);
}

// round 7
// speedup vs baseline: 1.2918x; 1.0460x over previous
#include <cuda_runtime.h>
#include <cstdint>

// ---------------- problem constants ----------------
#define NMAX 10000
#define EMAX 640000
#define DDIM 128
#define EDIM 64
#define HDS  8
#define OUTD 128

// ---------------- device scratch ----------------
__device__ __align__(16) float g_q[NMAX * DDIM];
__device__ __align__(16) float g_k[NMAX * DDIM];
__device__ __align__(16) float g_u[NMAX * OUTD];
__device__ __align__(16) float g_v[NMAX * OUTD];
__device__ __align__(16) float g_P[NMAX * HDS * OUTD];
__device__ __align__(16) float g_a[EMAX * HDS];     // exp(logit), by ORIGINAL edge id
__device__ __align__(16) float g_s[NMAX * HDS];     // segment sums -> 0.25/(s+eps)
__device__ __align__(16) float g_WcT[OUTD * OUTD];
__device__ __align__(16) float2 g_wdup[EDIM * DDIM]; // wdup[jj][d] = {Wre[d][jj], Wre[d][jj]}
__device__ int g_is64;
__device__ int g_nj[EMAX];
__device__ int g_ni[EMAX];
__device__ int g_cnt[NMAX];
__device__ int g_start[NMAX + 1];
__device__ int g_off[NMAX];
__device__ int g_elist[EMAX];

// ---------------- helpers ----------------
__device__ __forceinline__ unsigned long long pack2(float x) {
    unsigned long long r; unsigned u = __float_as_uint(x);
    asm("mov.b64 %0, {%1, %1};" : "=l"(r) : "r"(u));
    return r;
}
__device__ __forceinline__ void fma2(unsigned long long& d, unsigned long long a, unsigned long long b) {
    asm("fma.rn.f32x2 %0, %1, %2, %0;" : "+l"(d) : "l"(a), "l"(b));
}
__device__ __forceinline__ void unpack2(unsigned long long v, float& x, float& y) {
    unsigned a, b;
    asm("mov.b64 {%0, %1}, %2;" : "=r"(a), "=r"(b) : "l"(v));
    x = __uint_as_float(a); y = __uint_as_float(b);
}
__device__ __forceinline__ float siluf(float x) { return x / (1.0f + __expf(-x)); }
__device__ __forceinline__ int load_idx(const void* eidx, int is64, long long pos) {
    return is64 ? (int)((const long long*)eidx)[pos] : ((const int*)eidx)[pos];
}

// ---------------- 0) detect int64 vs int32 edge_index ----------------
__global__ void detect_idx_kernel(const unsigned* __restrict__ w) {
    __shared__ int any;
    if (threadIdx.x == 0) any = 0;
    __syncthreads();
    if (w[threadIdx.x * 2 + 1] != 0u) any = 1;
    __syncthreads();
    if (threadIdx.x == 0) g_is64 = (any == 0) ? 1 : 0;
}

// ---------------- 1) init ----------------
__global__ void init_kernel(const float* __restrict__ Wc, int NH, int Nn) {
    int i = blockIdx.x * blockDim.x + threadIdx.x;
    if (i < NH) g_s[i] = 0.0f;
    if (i < Nn) g_cnt[i] = 0;
    if (i < OUTD * OUTD) {
        int o = i >> 7, d = i & 127;
        g_WcT[d * OUTD + o] = Wc[i];
    }
}

// ---------------- 2) convert indices + histogram, fused with Wre duplication ----------------
// First eBlocks blocks handle edges; last 32 blocks build g_wdup.
__global__ void convert_hist_wdup_kernel(const void* __restrict__ eidx,
                                         const float* __restrict__ Wre,
                                         int E, int eBlocks) {
    if (blockIdx.x >= eBlocks) {
        int idx = (blockIdx.x - eBlocks) * blockDim.x + threadIdx.x;  // 0..8191
        if (idx < EDIM * DDIM) {
            int jj = idx >> 7, d = idx & 127;
            float v = Wre[d * EDIM + jj];
            g_wdup[jj * 128 + d] = make_float2(v, v);
        }
        return;
    }
    int e = blockIdx.x * blockDim.x + threadIdx.x;
    if (e >= E) return;
    int is64 = g_is64;
    int nj = load_idx(eidx, is64, e);
    int ni = load_idx(eidx, is64, (long long)E + e);
    g_nj[e] = nj;
    g_ni[e] = ni;
    atomicAdd(&g_cnt[nj], 1);
}

// ---------------- 3a) fused node GEMM (q, k, silu-u) ----------------
#define PADW 132
#define PADA 36
__global__ __launch_bounds__(256)
void gemm3_kernel(const float* __restrict__ A,
                  const float* __restrict__ W0, const float* __restrict__ B0,
                  const float* __restrict__ W1p, const float* __restrict__ B1,
                  const float* __restrict__ W2p, const float* __restrict__ B2,
                  float* __restrict__ C0, float* __restrict__ C1, float* __restrict__ C2,
                  int M) {
    const float* W = (blockIdx.y == 0) ? W0 : (blockIdx.y == 1) ? W1p : W2p;
    const float* bias = (blockIdx.y == 0) ? B0 : (blockIdx.y == 1) ? B1 : B2;
    float* C = (blockIdx.y == 0) ? C0 : (blockIdx.y == 1) ? C1 : C2;
    int act = (blockIdx.y == 2);

    __shared__ float wsm[64 * PADW];
    __shared__ float asmv[64 * PADA];
    __shared__ float bsm[128];

    int tid = threadIdx.x;
    int row0 = blockIdx.x * 32;
    int nIdx = tid & 31, mIdx = tid >> 5;
    int n0 = nIdx * 4, m0 = mIdx * 4;
    if (tid < 128) bsm[tid] = bias[tid];

    unsigned long long acc2[4][2] = {};
    for (int kt = 0; kt < DDIM; kt += 64) {
        for (int idx = tid; idx < 128 * 64; idx += 256) {
            int o = idx >> 6, jj = idx & 63;
            wsm[jj * PADW + o] = W[o * DDIM + kt + jj];
        }
        for (int idx = tid; idx < 32 * 64; idx += 256) {
            int m = idx >> 6, jj = idx & 63;
            int r = row0 + m;
            asmv[jj * PADA + m] = (r < M) ? A[r * DDIM + kt + jj] : 0.0f;
        }
        __syncthreads();
        #pragma unroll 16
        for (int j = 0; j < 64; j++) {
            ulonglong2 wv = *(const ulonglong2*)&wsm[j * PADW + n0];
            float4 av = *(const float4*)&asmv[j * PADA + m0];
            unsigned long long a0 = pack2(av.x), a1 = pack2(av.y),
                               a2 = pack2(av.z), a3 = pack2(av.w);
            fma2(acc2[0][0], a0, wv.x); fma2(acc2[0][1], a0, wv.y);
            fma2(acc2[1][0], a1, wv.x); fma2(acc2[1][1], a1, wv.y);
            fma2(acc2[2][0], a2, wv.x); fma2(acc2[2][1], a2, wv.y);
            fma2(acc2[3][0], a3, wv.x); fma2(acc2[3][1], a3, wv.y);
        }
        __syncthreads();
    }
    #pragma unroll
    for (int mi = 0; mi < 4; mi++) {
        int r = row0 + m0 + mi;
        if (r < M) {
            float v0, v1, v2, v3;
            unpack2(acc2[mi][0], v0, v1);
            unpack2(acc2[mi][1], v2, v3);
            v0 += bsm[n0 + 0]; v1 += bsm[n0 + 1]; v2 += bsm[n0 + 2]; v3 += bsm[n0 + 3];
            if (act) { v0 = siluf(v0); v1 = siluf(v1); v2 = siluf(v2); v3 = siluf(v3); }
            *(float4*)&C[r * 128 + n0] = make_float4(v0, v1, v2, v3);
        }
    }
}

// ---------------- 3b) v = u @ W2^T + b2 ----------------
__global__ __launch_bounds__(256)
void gemm_kernel(const float* __restrict__ A, const float* __restrict__ W,
                 const float* __restrict__ bias, float* __restrict__ C, int M) {
    __shared__ float wsm[64 * PADW];
    __shared__ float asmv[64 * PADA];
    __shared__ float bsm[128];

    int tid = threadIdx.x;
    int row0 = blockIdx.x * 32;
    int nIdx = tid & 31, mIdx = tid >> 5;
    int n0 = nIdx * 4, m0 = mIdx * 4;
    if (tid < 128) bsm[tid] = bias[tid];

    unsigned long long acc2[4][2] = {};
    for (int kt = 0; kt < OUTD; kt += 64) {
        for (int idx = tid; idx < 128 * 64; idx += 256) {
            int o = idx >> 6, jj = idx & 63;
            wsm[jj * PADW + o] = W[o * OUTD + kt + jj];
        }
        for (int idx = tid; idx < 32 * 64; idx += 256) {
            int m = idx >> 6, jj = idx & 63;
            int r = row0 + m;
            asmv[jj * PADA + m] = (r < M) ? A[r * OUTD + kt + jj] : 0.0f;
        }
        __syncthreads();
        #pragma unroll 16
        for (int j = 0; j < 64; j++) {
            ulonglong2 wv = *(const ulonglong2*)&wsm[j * PADW + n0];
            float4 av = *(const float4*)&asmv[j * PADA + m0];
            unsigned long long a0 = pack2(av.x), a1 = pack2(av.y),
                               a2 = pack2(av.z), a3 = pack2(av.w);
            fma2(acc2[0][0], a0, wv.x); fma2(acc2[0][1], a0, wv.y);
            fma2(acc2[1][0], a1, wv.x); fma2(acc2[1][1], a1, wv.y);
            fma2(acc2[2][0], a2, wv.x); fma2(acc2[2][1], a2, wv.y);
            fma2(acc2[3][0], a3, wv.x); fma2(acc2[3][1], a3, wv.y);
        }
        __syncthreads();
    }
    #pragma unroll
    for (int mi = 0; mi < 4; mi++) {
        int r = row0 + m0 + mi;
        if (r < M) {
            float v0, v1, v2, v3;
            unpack2(acc2[mi][0], v0, v1);
            unpack2(acc2[mi][1], v2, v3);
            v0 += bsm[n0 + 0]; v1 += bsm[n0 + 1]; v2 += bsm[n0 + 2]; v3 += bsm[n0 + 3];
            *(float4*)&C[r * 128 + n0] = make_float4(v0, v1, v2, v3);
        }
    }
}

// ---------------- 4) sort: scan + scatter ----------------
__global__ __launch_bounds__(1024)
void scan_kernel(int Nn) {
    __shared__ int part[1024];
    int t = threadIdx.x;
    int chunk = (Nn + 1023) >> 10;
    int base = t * chunk;
    int local[16];
    int sum = 0;
    for (int i = 0; i < chunk; i++) {
        int idx = base + i;
        int c = (idx < Nn) ? g_cnt[idx] : 0;
        local[i] = sum; sum += c;
    }
    part[t] = sum;
    __syncthreads();
    for (int off = 1; off < 1024; off <<= 1) {
        int v = (t >= off) ? part[t - off] : 0;
        __syncthreads();
        part[t] += v;
        __syncthreads();
    }
    int pre = (t > 0) ? part[t - 1] : 0;
    for (int i = 0; i < chunk; i++) {
        int idx = base + i;
        if (idx < Nn) { int s0 = pre + local[i]; g_start[idx] = s0; g_off[idx] = s0; }
    }
    if (t == 0) g_start[Nn] = part[1023];
}

__global__ void scatter_kernel(int E) {
    int e = blockIdx.x * blockDim.x + threadIdx.x;
    if (e >= E) return;
    int nj = g_nj[e];
    int pos = atomicAdd(&g_off[nj], 1);
    g_elist[pos] = e;
}

// ---------------- 5) edge logits: double-buffered re GEMM + q*k dot + exp + segment sum ----------------
// 128 edges/block, 256 threads, K chunked by 16, ping-pong staging (dynamic smem).
#define ELB 128
#define KC 16
#define WD_FLOATS (KC * 128 * 2)     // float2 per chunk, as floats: 4096
#define TS_FLOATS (KC * 132)         // 2112
// dynamic smem layout (floats): wd[2][4096], ts[2][2112], bre[128]
#define OFF_WD0 0
#define OFF_WD1 4096
#define OFF_TS0 8192
#define OFF_TS1 10304
#define OFF_BRE 12416
#define EL_SMEM ((12416 + 128) * 4)  // 50176 bytes

__global__ __launch_bounds__(256, 2)
void edge_logits_kernel(const float* __restrict__ T, const float* __restrict__ bre, int E) {
    extern __shared__ float sm[];
    int tid = threadIdx.x;
    int warp = tid >> 5, lane = tid & 31;
    int eBase = blockIdx.x * ELB;
    if (tid < 128) sm[OFF_BRE + tid] = bre[tid];

    int d0 = lane * 4;
    unsigned long long acc[8][4] = {};    // [edge-pair][d] ; pair p = local edges (2p, 2p+1)

    // staging lambda (chunk kc into buffer buf)
    auto stage = [&](int buf, int kc) {
        float4* dst = (float4*)(sm + (buf ? OFF_WD1 : OFF_WD0));
        const float4* src = (const float4*)(g_wdup + kc * KC * 128);
        #pragma unroll
        for (int i = 0; i < 4; i++) dst[tid + i * 256] = src[tid + i * 256];
        float* tb = sm + (buf ? OFF_TS1 : OFF_TS0);
        #pragma unroll
        for (int idx = tid; idx < ELB * KC; idx += 256) {
            int jj = idx & (KC - 1), eL = idx >> 4;
            int e = eBase + eL;
            tb[jj * 132 + eL] = (e < E) ? T[(long long)e * EDIM + kc * KC + jj] : 0.0f;
        }
    };

    stage(0, 0);
    __syncthreads();

    for (int kc = 0; kc < EDIM / KC; kc++) {
        int buf = kc & 1;
        if (kc + 1 < EDIM / KC) stage(buf ^ 1, kc + 1);

        const float2* wdsm = (const float2*)(sm + (buf ? OFF_WD1 : OFF_WD0));
        const float*  tsm  = sm + (buf ? OFF_TS1 : OFF_TS0);
        #pragma unroll
        for (int j = 0; j < KC; j++) {
            ulonglong2 w01 = *(const ulonglong2*)&wdsm[j * 128 + d0];
            ulonglong2 w23 = *(const ulonglong2*)&wdsm[j * 128 + d0 + 2];
            const ulonglong2* tp = (const ulonglong2*)&tsm[j * 132 + warp * 16];
            ulonglong2 tA = tp[0], tB = tp[1], tC = tp[2], tD = tp[3];   // warp-uniform broadcasts
            fma2(acc[0][0], tA.x, w01.x); fma2(acc[0][1], tA.x, w01.y); fma2(acc[0][2], tA.x, w23.x); fma2(acc[0][3], tA.x, w23.y);
            fma2(acc[1][0], tA.y, w01.x); fma2(acc[1][1], tA.y, w01.y); fma2(acc[1][2], tA.y, w23.x); fma2(acc[1][3], tA.y, w23.y);
            fma2(acc[2][0], tB.x, w01.x); fma2(acc[2][1], tB.x, w01.y); fma2(acc[2][2], tB.x, w23.x); fma2(acc[2][3], tB.x, w23.y);
            fma2(acc[3][0], tB.y, w01.x); fma2(acc[3][1], tB.y, w01.y); fma2(acc[3][2], tB.y, w23.x); fma2(acc[3][3], tB.y, w23.y);
            fma2(acc[4][0], tC.x, w01.x); fma2(acc[4][1], tC.x, w01.y); fma2(acc[4][2], tC.x, w23.x); fma2(acc[4][3], tC.x, w23.y);
            fma2(acc[5][0], tC.y, w01.x); fma2(acc[5][1], tC.y, w01.y); fma2(acc[5][2], tC.y, w23.x); fma2(acc[5][3], tC.y, w23.y);
            fma2(acc[6][0], tD.x, w01.x); fma2(acc[6][1], tD.x, w01.y); fma2(acc[6][2], tD.x, w23.x); fma2(acc[6][3], tD.x, w23.y);
            fma2(acc[7][0], tD.y, w01.x); fma2(acc[7][1], tD.y, w01.y); fma2(acc[7][2], tD.y, w23.x); fma2(acc[7][3], tD.y, w23.y);
        }
        __syncthreads();
    }

    int head = lane >> 2;
    const float* bsm = sm + OFF_BRE;
    float b0 = bsm[d0 + 0], b1 = bsm[d0 + 1], b2 = bsm[d0 + 2], b3 = bsm[d0 + 3];

    #pragma unroll
    for (int ei = 0; ei < 16; ei++) {
        int e = eBase + warp * 16 + ei;   // uniform within warp
        if (e >= E) continue;
        int nj = g_nj[e];
        int ni = g_ni[e];
        float4 q4 = *(const float4*)&g_q[ni * 128 + d0];
        float4 k4 = *(const float4*)&g_k[nj * 128 + d0];
        int p = ei >> 1;
        float lo0, hi0, lo1, hi1, lo2, hi2, lo3, hi3;
        unpack2(acc[p][0], lo0, hi0);
        unpack2(acc[p][1], lo1, hi1);
        unpack2(acc[p][2], lo2, hi2);
        unpack2(acc[p][3], lo3, hi3);
        float x0 = (ei & 1) ? hi0 : lo0;
        float x1 = (ei & 1) ? hi1 : lo1;
        float x2 = (ei & 1) ? hi2 : lo2;
        float x3 = (ei & 1) ? hi3 : lo3;
        x0 = siluf(x0 + b0); x1 = siluf(x1 + b1);
        x2 = siluf(x2 + b2); x3 = siluf(x3 + b3);
        float part = x0 * q4.x * k4.x + x1 * q4.y * k4.y
                   + x2 * q4.z * k4.z + x3 * q4.w * k4.w;
        part += __shfl_xor_sync(0xffffffffu, part, 1);
        part += __shfl_xor_sync(0xffffffffu, part, 2);
        if ((lane & 3) == 0) {
            float ex = __expf(fminf(part, 80.0f));  // shift-free softmax (logits bounded)
            g_a[e * 8 + head] = ex;
            atomicAdd(&g_s[ni * 8 + head], ex);
        }
    }
}

// ---------------- 6) per-node P, fused with sum inversion ----------------
__global__ __launch_bounds__(256)
void pmat_sinv_kernel(int Nn) {
    // fused: invert softmax sums (independent work, grid covers NH = Nn*8 <= grid*threads)
    {
        int i = blockIdx.x * blockDim.x + threadIdx.x;
        if (i < Nn * HDS) g_s[i] = 0.25f / (g_s[i] + 1e-16f);
    }

    int tid = threadIdx.x;
    int h = tid >> 5;
    int o0 = (tid & 31) * 4;
    int n0 = blockIdx.x * 8;

    float acc[8][4];
    #pragma unroll
    for (int n = 0; n < 8; n++) { acc[n][0] = acc[n][1] = acc[n][2] = acc[n][3] = 0.0f; }

    #pragma unroll
    for (int dd = 0; dd < 16; dd++) {
        int d = h * 16 + dd;
        float4 w4 = *(const float4*)&g_WcT[d * OUTD + o0];
        #pragma unroll
        for (int n = 0; n < 8; n++) {
            int r = n0 + n;
            float vv = (r < Nn) ? g_v[r * OUTD + d] : 0.0f;
            acc[n][0] = fmaf(vv, w4.x, acc[n][0]);
            acc[n][1] = fmaf(vv, w4.y, acc[n][1]);
            acc[n][2] = fmaf(vv, w4.z, acc[n][2]);
            acc[n][3] = fmaf(vv, w4.w, acc[n][3]);
        }
    }
    #pragma unroll
    for (int n = 0; n < 8; n++) {
        int r = n0 + n;
        if (r < Nn) {
            *(float4*)&g_P[((r * 8 + h) * OUTD) + o0] =
                make_float4(acc[n][0], acc[n][1], acc[n][2], acc[n][3]);
        }
    }
}

// ---------------- 7) output: block per node nj, P slice in registers ----------------
__global__ __launch_bounds__(256)
void out_kernel(const float* __restrict__ bc, float* __restrict__ outp, int E) {
    int n = blockIdx.x;
    int start = g_start[n], end = g_start[n + 1];
    if (start == end) return;
    int warp = threadIdx.x >> 5, lane = threadIdx.x & 31;
    int o0 = lane * 4;

    float4 P4[8];
    #pragma unroll
    for (int h = 0; h < 8; h++)
        P4[h] = *(const float4*)&g_P[((n * 8 + h) * OUTD) + o0];
    float4 bc4 = *(const float4*)&bc[o0];

    for (int i = start + warp; i < end; i += 8) {
        int e = g_elist[i];
        float w = 0.0f;
        if (lane < 8) {
            int ni = g_ni[e];
            w = g_a[e * 8 + lane] * g_s[ni * 8 + lane];   // g_s holds 0.25/(s+eps)
        }
        float4 acc = bc4;
        #pragma unroll
        for (int h = 0; h < 8; h++) {
            float wh = __shfl_sync(0xffffffffu, w, h);
            acc.x = fmaf(wh, P4[h].x, acc.x);
            acc.y = fmaf(wh, P4[h].y, acc.y);
            acc.z = fmaf(wh, P4[h].z, acc.z);
            acc.w = fmaf(wh, P4[h].w, acc.w);
        }
        *(float4*)&outp[(long long)e * 128 + o0] = acc;
    }
}

// ---------------- host launcher ----------------
extern "C" void kernel_launch(void* const* d_in, const int* in_sizes, int n_in,
                              void* d_out, int out_size) {
    const float* h    = (const float*)d_in[0];
    const float* tij  = (const float*)d_in[1];
    const void*  eidx = d_in[2];
    const float* Wq   = (const float*)d_in[3];
    const float* bq   = (const float*)d_in[4];
    const float* Wk   = (const float*)d_in[5];
    const float* bk   = (const float*)d_in[6];
    const float* W1   = (const float*)d_in[7];
    const float* b1   = (const float*)d_in[8];
    const float* W2   = (const float*)d_in[9];
    const float* b2   = (const float*)d_in[10];
    const float* Wre  = (const float*)d_in[11];
    const float* bre  = (const float*)d_in[12];
    const float* Wc   = (const float*)d_in[13];
    const float* bc   = (const float*)d_in[14];

    int Nn = in_sizes[0] / DDIM;     // 10000
    int E  = in_sizes[1] / EDIM;     // 640000

    float *pq, *pk, *pu, *pv;
    cudaGetSymbolAddress((void**)&pq, g_q);
    cudaGetSymbolAddress((void**)&pk, g_k);
    cudaGetSymbolAddress((void**)&pu, g_u);
    cudaGetSymbolAddress((void**)&pv, g_v);

    static int smem_set = 0;
    if (!smem_set) {
        cudaFuncSetAttribute(edge_logits_kernel, cudaFuncAttributeMaxDynamicSharedMemorySize, EL_SMEM);
        smem_set = 1;
    }

    // 0) detect index width
    detect_idx_kernel<<<1, 1024>>>((const unsigned*)eidx);

    // 1) init
    {
        int total = Nn * HDS;
        if (total < OUTD * OUTD) total = OUTD * OUTD;
        if (total < Nn) total = Nn;
        init_kernel<<<(total + 255) / 256, 256>>>(Wc, Nn * HDS, Nn);
    }

    // 2) convert indices + histogram + wdup prep (fused)
    {
        int eBlocks = (E + 255) / 256;
        convert_hist_wdup_kernel<<<eBlocks + 32, 256>>>(eidx, Wre, E, eBlocks);
    }

    // 3) node projections
    int gb = (Nn + 31) / 32;
    {
        dim3 grid(gb, 3);
        gemm3_kernel<<<grid, 256>>>(h, Wq, bq, Wk, bk, W1, b1, pq, pk, pu, Nn);
    }
    gemm_kernel<<<gb, 256>>>(pu, W2, b2, pv, Nn);

    // 4) sort by nj (for out_kernel locality)
    scan_kernel<<<1, 1024>>>(Nn);
    scatter_kernel<<<(E + 255) / 256, 256>>>(E);

    // 5) edge logits + exp + segment sum (double-buffered staging)
    edge_logits_kernel<<<(E + ELB - 1) / ELB, 256, EL_SMEM>>>(tij, bre, E);

    // 6) P matrix + sum inversion (fused)
    pmat_sinv_kernel<<<(Nn + 7) / 8, 256>>>(Nn);

    // 7) output
    out_kernel<<<Nn, 256>>>(bc, (float*)d_out, E);
}

// round 8
// speedup vs baseline: 1.3430x; 1.0397x over previous
#include <cuda_runtime.h>
#include <cstdint>

// ---------------- problem constants ----------------
#define NMAX 10000
#define EMAX 640000
#define DDIM 128
#define EDIM 64
#define HDS  8
#define OUTD 128

// ---------------- device scratch ----------------
__device__ __align__(16) float g_q[NMAX * DDIM];
__device__ __align__(16) float g_k[NMAX * DDIM];
__device__ __align__(16) float g_u[NMAX * OUTD];
__device__ __align__(16) float g_v[NMAX * OUTD];
__device__ __align__(16) float g_P[NMAX * HDS * OUTD];
__device__ __align__(16) float g_a[EMAX * HDS];     // exp(logit), by ORIGINAL edge id
__device__ __align__(16) float g_s[NMAX * HDS];     // segment sums -> 0.25/(s+eps)
__device__ __align__(16) float g_WcT[OUTD * OUTD];
__device__ __align__(16) float2 g_wdup[EDIM * DDIM]; // wdup[jj][d] = {Wre[d][jj], Wre[d][jj]}
__device__ int g_is64;
__device__ int g_nj[EMAX];
__device__ int g_ni[EMAX];
__device__ int g_cnt[NMAX];
__device__ int g_start[NMAX + 1];
__device__ int g_off[NMAX];
__device__ int g_elist[EMAX];

// ---------------- helpers ----------------
__device__ __forceinline__ unsigned long long pack2(float x) {
    unsigned long long r; unsigned u = __float_as_uint(x);
    asm("mov.b64 %0, {%1, %1};" : "=l"(r) : "r"(u));
    return r;
}
__device__ __forceinline__ void fma2(unsigned long long& d, unsigned long long a, unsigned long long b) {
    asm("fma.rn.f32x2 %0, %1, %2, %0;" : "+l"(d) : "l"(a), "l"(b));
}
__device__ __forceinline__ void unpack2(unsigned long long v, float& x, float& y) {
    unsigned a, b;
    asm("mov.b64 {%0, %1}, %2;" : "=r"(a), "=r"(b) : "l"(v));
    x = __uint_as_float(a); y = __uint_as_float(b);
}
// fast silu: single MUFU.EX2 + MUFU.RCP (no IEEE div sequence)
__device__ __forceinline__ float siluf(float x) { return __fdividef(x, 1.0f + __expf(-x)); }
__device__ __forceinline__ int load_idx(const void* eidx, int is64, long long pos) {
    return is64 ? (int)((const long long*)eidx)[pos] : ((const int*)eidx)[pos];
}

// ---------------- 0) detect int64 vs int32 edge_index ----------------
__global__ void detect_idx_kernel(const unsigned* __restrict__ w) {
    __shared__ int any;
    if (threadIdx.x == 0) any = 0;
    __syncthreads();
    if (w[threadIdx.x * 2 + 1] != 0u) any = 1;
    __syncthreads();
    if (threadIdx.x == 0) g_is64 = (any == 0) ? 1 : 0;
}

// ---------------- 1) init ----------------
__global__ void init_kernel(const float* __restrict__ Wc, int NH, int Nn) {
    int i = blockIdx.x * blockDim.x + threadIdx.x;
    if (i < NH) g_s[i] = 0.0f;
    if (i < Nn) g_cnt[i] = 0;
    if (i < OUTD * OUTD) {
        int o = i >> 7, d = i & 127;
        g_WcT[d * OUTD + o] = Wc[i];
    }
}

// ---------------- 2) convert indices + histogram, fused with Wre duplication ----------------
__global__ void convert_hist_wdup_kernel(const void* __restrict__ eidx,
                                         const float* __restrict__ Wre,
                                         int E, int eBlocks) {
    if (blockIdx.x >= eBlocks) {
        int idx = (blockIdx.x - eBlocks) * blockDim.x + threadIdx.x;
        if (idx < EDIM * DDIM) {
            int jj = idx >> 7, d = idx & 127;
            float v = Wre[d * EDIM + jj];
            g_wdup[jj * 128 + d] = make_float2(v, v);
        }
        return;
    }
    int e = blockIdx.x * blockDim.x + threadIdx.x;
    if (e >= E) return;
    int is64 = g_is64;
    int nj = load_idx(eidx, is64, e);
    int ni = load_idx(eidx, is64, (long long)E + e);
    g_nj[e] = nj;
    g_ni[e] = ni;
    atomicAdd(&g_cnt[nj], 1);
}

// ---------------- 3a) fused node GEMM (q, k, silu-u) ----------------
#define PADW 132
#define PADA 36
__global__ __launch_bounds__(256)
void gemm3_kernel(const float* __restrict__ A,
                  const float* __restrict__ W0, const float* __restrict__ B0,
                  const float* __restrict__ W1p, const float* __restrict__ B1,
                  const float* __restrict__ W2p, const float* __restrict__ B2,
                  float* __restrict__ C0, float* __restrict__ C1, float* __restrict__ C2,
                  int M) {
    const float* W = (blockIdx.y == 0) ? W0 : (blockIdx.y == 1) ? W1p : W2p;
    const float* bias = (blockIdx.y == 0) ? B0 : (blockIdx.y == 1) ? B1 : B2;
    float* C = (blockIdx.y == 0) ? C0 : (blockIdx.y == 1) ? C1 : C2;
    int act = (blockIdx.y == 2);

    __shared__ float wsm[64 * PADW];
    __shared__ float asmv[64 * PADA];
    __shared__ float bsm[128];

    int tid = threadIdx.x;
    int row0 = blockIdx.x * 32;
    int nIdx = tid & 31, mIdx = tid >> 5;
    int n0 = nIdx * 4, m0 = mIdx * 4;
    if (tid < 128) bsm[tid] = bias[tid];

    unsigned long long acc2[4][2] = {};
    for (int kt = 0; kt < DDIM; kt += 64) {
        for (int idx = tid; idx < 128 * 64; idx += 256) {
            int o = idx >> 6, jj = idx & 63;
            wsm[jj * PADW + o] = W[o * DDIM + kt + jj];
        }
        for (int idx = tid; idx < 32 * 64; idx += 256) {
            int m = idx >> 6, jj = idx & 63;
            int r = row0 + m;
            asmv[jj * PADA + m] = (r < M) ? A[r * DDIM + kt + jj] : 0.0f;
        }
        __syncthreads();
        #pragma unroll 16
        for (int j = 0; j < 64; j++) {
            ulonglong2 wv = *(const ulonglong2*)&wsm[j * PADW + n0];
            float4 av = *(const float4*)&asmv[j * PADA + m0];
            unsigned long long a0 = pack2(av.x), a1 = pack2(av.y),
                               a2 = pack2(av.z), a3 = pack2(av.w);
            fma2(acc2[0][0], a0, wv.x); fma2(acc2[0][1], a0, wv.y);
            fma2(acc2[1][0], a1, wv.x); fma2(acc2[1][1], a1, wv.y);
            fma2(acc2[2][0], a2, wv.x); fma2(acc2[2][1], a2, wv.y);
            fma2(acc2[3][0], a3, wv.x); fma2(acc2[3][1], a3, wv.y);
        }
        __syncthreads();
    }
    #pragma unroll
    for (int mi = 0; mi < 4; mi++) {
        int r = row0 + m0 + mi;
        if (r < M) {
            float v0, v1, v2, v3;
            unpack2(acc2[mi][0], v0, v1);
            unpack2(acc2[mi][1], v2, v3);
            v0 += bsm[n0 + 0]; v1 += bsm[n0 + 1]; v2 += bsm[n0 + 2]; v3 += bsm[n0 + 3];
            if (act) { v0 = siluf(v0); v1 = siluf(v1); v2 = siluf(v2); v3 = siluf(v3); }
            *(float4*)&C[r * 128 + n0] = make_float4(v0, v1, v2, v3);
        }
    }
}

// ---------------- 3b) v = u @ W2^T + b2 ----------------
__global__ __launch_bounds__(256)
void gemm_kernel(const float* __restrict__ A, const float* __restrict__ W,
                 const float* __restrict__ bias, float* __restrict__ C, int M) {
    __shared__ float wsm[64 * PADW];
    __shared__ float asmv[64 * PADA];
    __shared__ float bsm[128];

    int tid = threadIdx.x;
    int row0 = blockIdx.x * 32;
    int nIdx = tid & 31, mIdx = tid >> 5;
    int n0 = nIdx * 4, m0 = mIdx * 4;
    if (tid < 128) bsm[tid] = bias[tid];

    unsigned long long acc2[4][2] = {};
    for (int kt = 0; kt < OUTD; kt += 64) {
        for (int idx = tid; idx < 128 * 64; idx += 256) {
            int o = idx >> 6, jj = idx & 63;
            wsm[jj * PADW + o] = W[o * OUTD + kt + jj];
        }
        for (int idx = tid; idx < 32 * 64; idx += 256) {
            int m = idx >> 6, jj = idx & 63;
            int r = row0 + m;
            asmv[jj * PADA + m] = (r < M) ? A[r * OUTD + kt + jj] : 0.0f;
        }
        __syncthreads();
        #pragma unroll 16
        for (int j = 0; j < 64; j++) {
            ulonglong2 wv = *(const ulonglong2*)&wsm[j * PADW + n0];
            float4 av = *(const float4*)&asmv[j * PADA + m0];
            unsigned long long a0 = pack2(av.x), a1 = pack2(av.y),
                               a2 = pack2(av.z), a3 = pack2(av.w);
            fma2(acc2[0][0], a0, wv.x); fma2(acc2[0][1], a0, wv.y);
            fma2(acc2[1][0], a1, wv.x); fma2(acc2[1][1], a1, wv.y);
            fma2(acc2[2][0], a2, wv.x); fma2(acc2[2][1], a2, wv.y);
            fma2(acc2[3][0], a3, wv.x); fma2(acc2[3][1], a3, wv.y);
        }
        __syncthreads();
    }
    #pragma unroll
    for (int mi = 0; mi < 4; mi++) {
        int r = row0 + m0 + mi;
        if (r < M) {
            float v0, v1, v2, v3;
            unpack2(acc2[mi][0], v0, v1);
            unpack2(acc2[mi][1], v2, v3);
            v0 += bsm[n0 + 0]; v1 += bsm[n0 + 1]; v2 += bsm[n0 + 2]; v3 += bsm[n0 + 3];
            *(float4*)&C[r * 128 + n0] = make_float4(v0, v1, v2, v3);
        }
    }
}

// ---------------- 4) sort: scan + scatter ----------------
__global__ __launch_bounds__(1024)
void scan_kernel(int Nn) {
    __shared__ int part[1024];
    int t = threadIdx.x;
    int chunk = (Nn + 1023) >> 10;
    int base = t * chunk;
    int local[16];
    int sum = 0;
    for (int i = 0; i < chunk; i++) {
        int idx = base + i;
        int c = (idx < Nn) ? g_cnt[idx] : 0;
        local[i] = sum; sum += c;
    }
    part[t] = sum;
    __syncthreads();
    for (int off = 1; off < 1024; off <<= 1) {
        int v = (t >= off) ? part[t - off] : 0;
        __syncthreads();
        part[t] += v;
        __syncthreads();
    }
    int pre = (t > 0) ? part[t - 1] : 0;
    for (int i = 0; i < chunk; i++) {
        int idx = base + i;
        if (idx < Nn) { int s0 = pre + local[i]; g_start[idx] = s0; g_off[idx] = s0; }
    }
    if (t == 0) g_start[Nn] = part[1023];
}

__global__ void scatter_kernel(int E) {
    int e = blockIdx.x * blockDim.x + threadIdx.x;
    if (e >= E) return;
    int nj = g_nj[e];
    int pos = atomicAdd(&g_off[nj], 1);
    g_elist[pos] = e;
}

// ---------------- 5) edge logits: double-buffered re GEMM + q*k dot + exp + segment sum ----------------
#define ELB 128
#define KC 16
#define OFF_WD0 0
#define OFF_WD1 4096
#define OFF_TS0 8192
#define OFF_TS1 10304
#define OFF_BRE 12416
#define EL_SMEM ((12416 + 128) * 4)  // 50176 bytes

__global__ __launch_bounds__(256, 2)
void edge_logits_kernel(const float* __restrict__ T, const float* __restrict__ bre, int E) {
    extern __shared__ float sm[];
    int tid = threadIdx.x;
    int warp = tid >> 5, lane = tid & 31;
    int eBase = blockIdx.x * ELB;
    if (tid < 128) sm[OFF_BRE + tid] = bre[tid];

    int d0 = lane * 4;
    unsigned long long acc[8][4] = {};    // [edge-pair][d]

    auto stage = [&](int buf, int kc) {
        float4* dst = (float4*)(sm + (buf ? OFF_WD1 : OFF_WD0));
        const float4* src = (const float4*)(g_wdup + kc * KC * 128);
        #pragma unroll
        for (int i = 0; i < 4; i++) dst[tid + i * 256] = src[tid + i * 256];
        float* tb = sm + (buf ? OFF_TS1 : OFF_TS0);
        #pragma unroll
        for (int idx = tid; idx < ELB * KC; idx += 256) {
            int jj = idx & (KC - 1), eL = idx >> 4;
            int e = eBase + eL;
            tb[jj * 132 + eL] = (e < E) ? T[(long long)e * EDIM + kc * KC + jj] : 0.0f;
        }
    };

    stage(0, 0);
    __syncthreads();

    for (int kc = 0; kc < EDIM / KC; kc++) {
        int buf = kc & 1;
        if (kc + 1 < EDIM / KC) stage(buf ^ 1, kc + 1);

        const float2* wdsm = (const float2*)(sm + (buf ? OFF_WD1 : OFF_WD0));
        const float*  tsm  = sm + (buf ? OFF_TS1 : OFF_TS0);
        #pragma unroll
        for (int j = 0; j < KC; j++) {
            ulonglong2 w01 = *(const ulonglong2*)&wdsm[j * 128 + d0];
            ulonglong2 w23 = *(const ulonglong2*)&wdsm[j * 128 + d0 + 2];
            const ulonglong2* tp = (const ulonglong2*)&tsm[j * 132 + warp * 16];
            ulonglong2 tA = tp[0], tB = tp[1], tC = tp[2], tD = tp[3];
            fma2(acc[0][0], tA.x, w01.x); fma2(acc[0][1], tA.x, w01.y); fma2(acc[0][2], tA.x, w23.x); fma2(acc[0][3], tA.x, w23.y);
            fma2(acc[1][0], tA.y, w01.x); fma2(acc[1][1], tA.y, w01.y); fma2(acc[1][2], tA.y, w23.x); fma2(acc[1][3], tA.y, w23.y);
            fma2(acc[2][0], tB.x, w01.x); fma2(acc[2][1], tB.x, w01.y); fma2(acc[2][2], tB.x, w23.x); fma2(acc[2][3], tB.x, w23.y);
            fma2(acc[3][0], tB.y, w01.x); fma2(acc[3][1], tB.y, w01.y); fma2(acc[3][2], tB.y, w23.x); fma2(acc[3][3], tB.y, w23.y);
            fma2(acc[4][0], tC.x, w01.x); fma2(acc[4][1], tC.x, w01.y); fma2(acc[4][2], tC.x, w23.x); fma2(acc[4][3], tC.x, w23.y);
            fma2(acc[5][0], tC.y, w01.x); fma2(acc[5][1], tC.y, w01.y); fma2(acc[5][2], tC.y, w23.x); fma2(acc[5][3], tC.y, w23.y);
            fma2(acc[6][0], tD.x, w01.x); fma2(acc[6][1], tD.x, w01.y); fma2(acc[6][2], tD.x, w23.x); fma2(acc[6][3], tD.x, w23.y);
            fma2(acc[7][0], tD.y, w01.x); fma2(acc[7][1], tD.y, w01.y); fma2(acc[7][2], tD.y, w23.x); fma2(acc[7][3], tD.y, w23.y);
        }
        __syncthreads();
    }

    int head = lane >> 2;
    const float* bsm = sm + OFF_BRE;
    float b0 = bsm[d0 + 0], b1 = bsm[d0 + 1], b2 = bsm[d0 + 2], b3 = bsm[d0 + 3];

    #pragma unroll
    for (int ei = 0; ei < 16; ei++) {
        int e = eBase + warp * 16 + ei;
        if (e >= E) continue;
        int nj = g_nj[e];
        int ni = g_ni[e];
        float4 q4 = *(const float4*)&g_q[ni * 128 + d0];
        float4 k4 = *(const float4*)&g_k[nj * 128 + d0];
        int p = ei >> 1;
        float lo0, hi0, lo1, hi1, lo2, hi2, lo3, hi3;
        unpack2(acc[p][0], lo0, hi0);
        unpack2(acc[p][1], lo1, hi1);
        unpack2(acc[p][2], lo2, hi2);
        unpack2(acc[p][3], lo3, hi3);
        float x0 = (ei & 1) ? hi0 : lo0;
        float x1 = (ei & 1) ? hi1 : lo1;
        float x2 = (ei & 1) ? hi2 : lo2;
        float x3 = (ei & 1) ? hi3 : lo3;
        x0 = siluf(x0 + b0); x1 = siluf(x1 + b1);
        x2 = siluf(x2 + b2); x3 = siluf(x3 + b3);
        float part = x0 * q4.x * k4.x + x1 * q4.y * k4.y
                   + x2 * q4.z * k4.z + x3 * q4.w * k4.w;
        part += __shfl_xor_sync(0xffffffffu, part, 1);
        part += __shfl_xor_sync(0xffffffffu, part, 2);
        if ((lane & 3) == 0) {
            float ex = __expf(fminf(part, 80.0f));  // shift-free softmax (logits bounded)
            g_a[e * 8 + head] = ex;
            atomicAdd(&g_s[ni * 8 + head], ex);
        }
    }
}

// ---------------- 6) per-node P, fused with sum inversion ----------------
__global__ __launch_bounds__(256)
void pmat_sinv_kernel(int Nn) {
    {
        int i = blockIdx.x * blockDim.x + threadIdx.x;
        if (i < Nn * HDS) g_s[i] = 0.25f / (g_s[i] + 1e-16f);
    }

    int tid = threadIdx.x;
    int h = tid >> 5;
    int o0 = (tid & 31) * 4;
    int n0 = blockIdx.x * 8;

    float acc[8][4];
    #pragma unroll
    for (int n = 0; n < 8; n++) { acc[n][0] = acc[n][1] = acc[n][2] = acc[n][3] = 0.0f; }

    #pragma unroll
    for (int dd = 0; dd < 16; dd++) {
        int d = h * 16 + dd;
        float4 w4 = *(const float4*)&g_WcT[d * OUTD + o0];
        #pragma unroll
        for (int n = 0; n < 8; n++) {
            int r = n0 + n;
            float vv = (r < Nn) ? g_v[r * OUTD + d] : 0.0f;
            acc[n][0] = fmaf(vv, w4.x, acc[n][0]);
            acc[n][1] = fmaf(vv, w4.y, acc[n][1]);
            acc[n][2] = fmaf(vv, w4.z, acc[n][2]);
            acc[n][3] = fmaf(vv, w4.w, acc[n][3]);
        }
    }
    #pragma unroll
    for (int n = 0; n < 8; n++) {
        int r = n0 + n;
        if (r < Nn) {
            *(float4*)&g_P[((r * 8 + h) * OUTD) + o0] =
                make_float4(acc[n][0], acc[n][1], acc[n][2], acc[n][3]);
        }
    }
}

// ---------------- 7) output: block per node nj, P in registers, f32x2 accumulate ----------------
__global__ __launch_bounds__(256)
void out_kernel(const float* __restrict__ bc, float* __restrict__ outp, int E) {
    int n = blockIdx.x;
    int start = g_start[n], end = g_start[n + 1];
    if (start == end) return;
    int warp = threadIdx.x >> 5, lane = threadIdx.x & 31;
    int o0 = lane * 4;

    // per-lane P slice packed for f32x2: 8 heads x 2 pairs
    ulonglong2 P2[8];
    #pragma unroll
    for (int h = 0; h < 8; h++)
        P2[h] = *(const ulonglong2*)&g_P[((n * 8 + h) * OUTD) + o0];
    ulonglong2 bc2 = *(const ulonglong2*)&bc[o0];

    for (int i = start + warp; i < end; i += 8) {
        int e = g_elist[i];
        float w = 0.0f;
        if (lane < 8) {
            int ni = g_ni[e];
            w = g_a[e * 8 + lane] * g_s[ni * 8 + lane];   // g_s holds 0.25/(s+eps)
        }
        unsigned long long a0 = bc2.x, a1 = bc2.y;
        #pragma unroll
        for (int h = 0; h < 8; h++) {
            unsigned long long wh = pack2(__shfl_sync(0xffffffffu, w, h));
            fma2(a0, wh, P2[h].x);
            fma2(a1, wh, P2[h].y);
        }
        ulonglong2 res; res.x = a0; res.y = a1;
        *(ulonglong2*)&outp[(long long)e * 128 + o0] = res;
    }
}

// ---------------- host launcher ----------------
extern "C" void kernel_launch(void* const* d_in, const int* in_sizes, int n_in,
                              void* d_out, int out_size) {
    const float* h    = (const float*)d_in[0];
    const float* tij  = (const float*)d_in[1];
    const void*  eidx = d_in[2];
    const float* Wq   = (const float*)d_in[3];
    const float* bq   = (const float*)d_in[4];
    const float* Wk   = (const float*)d_in[5];
    const float* bk   = (const float*)d_in[6];
    const float* W1   = (const float*)d_in[7];
    const float* b1   = (const float*)d_in[8];
    const float* W2   = (const float*)d_in[9];
    const float* b2   = (const float*)d_in[10];
    const float* Wre  = (const float*)d_in[11];
    const float* bre  = (const float*)d_in[12];
    const float* Wc   = (const float*)d_in[13];
    const float* bc   = (const float*)d_in[14];

    int Nn = in_sizes[0] / DDIM;     // 10000
    int E  = in_sizes[1] / EDIM;     // 640000

    float *pq, *pk, *pu, *pv;
    cudaGetSymbolAddress((void**)&pq, g_q);
    cudaGetSymbolAddress((void**)&pk, g_k);
    cudaGetSymbolAddress((void**)&pu, g_u);
    cudaGetSymbolAddress((void**)&pv, g_v);

    static int smem_set = 0;
    if (!smem_set) {
        cudaFuncSetAttribute(edge_logits_kernel, cudaFuncAttributeMaxDynamicSharedMemorySize, EL_SMEM);
        smem_set = 1;
    }

    // 0) detect index width
    detect_idx_kernel<<<1, 1024>>>((const unsigned*)eidx);

    // 1) init
    {
        int total = Nn * HDS;
        if (total < OUTD * OUTD) total = OUTD * OUTD;
        if (total < Nn) total = Nn;
        init_kernel<<<(total + 255) / 256, 256>>>(Wc, Nn * HDS, Nn);
    }

    // 2) convert indices + histogram + wdup prep (fused)
    {
        int eBlocks = (E + 255) / 256;
        convert_hist_wdup_kernel<<<eBlocks + 32, 256>>>(eidx, Wre, E, eBlocks);
    }

    // 3) node projections
    int gb = (Nn + 31) / 32;
    {
        dim3 grid(gb, 3);
        gemm3_kernel<<<grid, 256>>>(h, Wq, bq, Wk, bk, W1, b1, pq, pk, pu, Nn);
    }
    gemm_kernel<<<gb, 256>>>(pu, W2, b2, pv, Nn);

    // 4) sort by nj (for out_kernel locality)
    scan_kernel<<<1, 1024>>>(Nn);
    scatter_kernel<<<(E + 255) / 256, 256>>>(E);

    // 5) edge logits + exp + segment sum (double-buffered staging)
    edge_logits_kernel<<<(E + ELB - 1) / ELB, 256, EL_SMEM>>>(tij, bre, E);

    // 6) P matrix + sum inversion (fused)
    pmat_sinv_kernel<<<(Nn + 7) / 8, 256>>>(Nn);

    // 7) output
    out_kernel<<<Nn, 256>>>(bc, (float*)d_out, E);
}